// round 11
// baseline (speedup 1.0000x reference)
#include <cuda_runtime.h>

#define N_EMIT 512
#define ZPL    8
#define ROI    20
#define NPX    400
#define SPL_D  64
#define SPL_H  40
#define SPL_W  40
#define CPITCH 404     // C_T row pitch (words); 404 = 4*101, float4-aligned rows
#define TPITCH 33      // fallback sval pitch

typedef unsigned long long u64;

__device__ __forceinline__ u64 ffma2(u64 a, u64 b, u64 c) {
    u64 d;
    asm("fma.rn.f32x2 %0, %1, %2, %3;" : "=l"(d) : "l"(a), "l"(b), "l"(c));
    return d;
}
__device__ __forceinline__ u64 fpack2(float lo, float hi) {
    u64 d;
    asm("mov.b64 %0, {%1, %2};" : "=l"(d) : "f"(lo), "f"(hi));
    return d;
}
__device__ __forceinline__ void funpack2(u64 a, float& lo, float& hi) {
    asm("mov.b64 {%0, %1}, %2;" : "=f"(lo), "=f"(hi) : "l"(a));
}

// One block = (echunk of 32 emitters) x (one z plane). 512 threads.
// Fast path: tiled GEMM D[400,32] = C_T[64,400]^T * W[64,32], 4px x 8em per thread.
__global__ __launch_bounds__(512, 1) void psf_fused(
    const float* __restrict__ pos,
    const float* __restrict__ inten,
    const float* __restrict__ bg,
    const float* __restrict__ coefs,
    float* __restrict__ out)
{
    extern __shared__ float dyn[];     // fast: C_T[64*CPITCH] ; fallback: sval[NPX*TPITCH]
    __shared__ float sW[64 * 32];      // W[t][e]
    __shared__ float sCsum[64];
    __shared__ float sRed[64][8];
    __shared__ float sScale[32];
    __shared__ float sBg[32];
    __shared__ float ssum[16][TPITCH]; // fallback only

    const int echunk = blockIdx.x & 15;
    const int z      = blockIdx.x >> 4;
    const int tid    = threadIdx.x;
    const int w      = tid >> 5;
    const int lane   = tid & 31;
    const int e      = echunk * 32 + lane;

    const float p0 = pos[e * 3 + 0];   // Y axis (faithful to reference)
    const float p1 = pos[e * 3 + 1];   // X axis
    const float p2 = pos[e * 3 + 2];   // Z axis

    // z terms (exact reference expressions)
    float pzf = (float)z - p2 + 28.0f;            // SPL_D/2 - ZPL/2
    float fz  = floorf(pzf);
    float dz  = pzf - fz;
    int   iz  = max(0, min((int)fz, SPL_D - 1));
    const int izoff = iz * SPL_H;

    float py0 = (0.0f - p0) + 10.0f;              // SPL_H/2 - ROI/2
    float fy0 = floorf(py0);
    float dy  = py0 - fy0;
    int   iy0 = (int)fy0;

    float px0 = (0.0f - p1) + 10.0f;              // SPL_W/2 - ROI/2
    float fx0 = floorf(px0);
    float dx  = px0 - fx0;
    int   ix0 = (int)fx0;

    // Genericity: canonical translated grid + per-row/col floor pattern.
    bool ok = (iy0 == 9) && (ix0 == 9) && (iz == z + 27);
    #pragma unroll
    for (int q = 1; q < ROI; q++) {
        ok &= floorf(((float)q - p0) + 10.0f) == (float)(iy0 + q);
        ok &= floorf(((float)q - p1) + 10.0f) == (float)(ix0 + q);
    }
    const bool fast = !__syncthreads_or(!ok);

    float dz2 = dz * dz, dz3 = dz2 * dz;

    if (fast) {
        // ---- Stage C_T[t][p ^ sc(t)] directly from global (transposed) ----
        // warp handles cell p; lane stores t = lane and t = lane+32.
        {
            const float* gbase = coefs +
                ((((size_t)(z + 27) * SPL_H + 9) * SPL_W + 9) << 6);
            const int sc1 = (lane >> 3) & 3;       // same for lane and lane+32
            #pragma unroll 5
            for (int r = 0; r < 25; r++) {
                int p = w * 25 + r;
                int y = p / 20;
                int x = p - y * 20;
                const float* cell = gbase + ((y * SPL_W + x) << 6);
                float v0 = cell[lane];             // coalesced 128B
                float v1 = cell[lane + 32];
                int pp = p ^ sc1;
                dyn[lane * CPITCH + pp]        = v0;   // conflict-free (swizzled)
                dyn[(lane + 32) * CPITCH + pp] = v1;
            }
        }
        __syncthreads();

        // ---- Csum[t] = sum_p C_T[t][p] (row sum; swizzle is a permutation) ----
        {
            const int t   = tid >> 3;
            const int seg = tid & 7;
            const float* row = dyn + t * CPITCH;
            float s = 0.0f;
            for (int g = seg; g < 100; g += 8) {
                float4 c = *(const float4*)(row + 4 * g);
                s += (c.x + c.y) + (c.z + c.w);
            }
            sRed[t][seg] = s;
        }
        __syncthreads();
        if (tid < 64) {
            float s = 0.0f;
            #pragma unroll
            for (int i = 0; i < 8; i++) s += sRed[tid][i];
            sCsum[tid] = s;
        }
        __syncthreads();

        // ---- W[t][e] + plane totals + scale/bg (warp 0, lane = emitter) ----
        if (w == 0) {
            float dx2 = dx * dx, dx3 = dx2 * dx;
            float dy2 = dy * dy, dy3 = dy2 * dy;
            float xp[4] = {1.0f, dx, dx2, dx3};
            float yp[4] = {1.0f, dy, dy2, dy3};
            float zp[4] = {1.0f, dz, dz2, dz3};
            float tot = 0.0f;
            #pragma unroll
            for (int a = 0; a < 4; a++) {
                #pragma unroll
                for (int b = 0; b < 4; b++) {
                    float wab = zp[a] * yp[b];
                    #pragma unroll
                    for (int c = 0; c < 4; c++) {
                        int t = (a * 4 + b) * 4 + c;
                        float wt = wab * xp[c];
                        sW[t * 32 + lane] = wt;            // banks = lane, conflict-free
                        tot = fmaf(wt, sCsum[t], tot);
                    }
                }
            }
            sScale[lane] = inten[e * ZPL + z] / tot;
            sBg[lane]    = bg[e * ZPL + z];
        }
        __syncthreads();

        // ---- GEMM: thread = (emg 0..3, pg 0..99) -> 4px x 8em tile ----
        if (tid < 400) {
            const int emg = tid / 100;
            const int pg  = tid - emg * 100;
            const float* crow = dyn + 4 * pg;        // + t*CPITCH per k
            const float* wrow = sW + emg * 8;        // + t*32    per k

            u64 acc[4][4];                           // [px d][em pair]
            #pragma unroll
            for (int d = 0; d < 4; d++)
                #pragma unroll
                for (int ep = 0; ep < 4; ep++) acc[d][ep] = 0ULL;

            #pragma unroll 4
            for (int t8 = 0; t8 < 8; t8++) {
                const int sc = t8 & 3;               // compile-time under unroll 4
                #pragma unroll
                for (int u = 0; u < 8; u++) {
                    const int t = t8 * 8 + u;
                    float4 c = *(const float4*)(crow + t * CPITCH);   // coalesced LDS.128
                    ulonglong2 wv0 = *(const ulonglong2*)(wrow + t * 32);      // (w0,w1),(w2,w3)
                    ulonglong2 wv1 = *(const ulonglong2*)(wrow + t * 32 + 4);  // (w4,w5),(w6,w7)
                    u64 c0 = fpack2(c.x, c.x);
                    u64 c1 = fpack2(c.y, c.y);
                    u64 c2 = fpack2(c.z, c.z);
                    u64 c3 = fpack2(c.w, c.w);
                    // component comp holds pixel offset comp ^ sc
                    acc[0 ^ sc][0] = ffma2(c0, wv0.x, acc[0 ^ sc][0]);
                    acc[0 ^ sc][1] = ffma2(c0, wv0.y, acc[0 ^ sc][1]);
                    acc[0 ^ sc][2] = ffma2(c0, wv1.x, acc[0 ^ sc][2]);
                    acc[0 ^ sc][3] = ffma2(c0, wv1.y, acc[0 ^ sc][3]);
                    acc[1 ^ sc][0] = ffma2(c1, wv0.x, acc[1 ^ sc][0]);
                    acc[1 ^ sc][1] = ffma2(c1, wv0.y, acc[1 ^ sc][1]);
                    acc[1 ^ sc][2] = ffma2(c1, wv1.x, acc[1 ^ sc][2]);
                    acc[1 ^ sc][3] = ffma2(c1, wv1.y, acc[1 ^ sc][3]);
                    acc[2 ^ sc][0] = ffma2(c2, wv0.x, acc[2 ^ sc][0]);
                    acc[2 ^ sc][1] = ffma2(c2, wv0.y, acc[2 ^ sc][1]);
                    acc[2 ^ sc][2] = ffma2(c2, wv1.x, acc[2 ^ sc][2]);
                    acc[2 ^ sc][3] = ffma2(c2, wv1.y, acc[2 ^ sc][3]);
                    acc[3 ^ sc][0] = ffma2(c3, wv0.x, acc[3 ^ sc][0]);
                    acc[3 ^ sc][1] = ffma2(c3, wv0.y, acc[3 ^ sc][1]);
                    acc[3 ^ sc][2] = ffma2(c3, wv1.x, acc[3 ^ sc][2]);
                    acc[3 ^ sc][3] = ffma2(c3, wv1.y, acc[3 ^ sc][3]);
                }
            }

            // ---- Epilogue: scale+bg, direct coalesced STG.128 ----
            #pragma unroll
            for (int ep = 0; ep < 4; ep++) {
                float4 va, vb;
                funpack2(acc[0][ep], va.x, vb.x);
                funpack2(acc[1][ep], va.y, vb.y);
                funpack2(acc[2][ep], va.z, vb.z);
                funpack2(acc[3][ep], va.w, vb.w);
                const int el = emg * 8 + 2 * ep;
                const float s0 = sScale[el],     b0 = sBg[el];
                const float s1 = sScale[el + 1], b1 = sBg[el + 1];
                va.x = fmaf(va.x, s0, b0); va.y = fmaf(va.y, s0, b0);
                va.z = fmaf(va.z, s0, b0); va.w = fmaf(va.w, s0, b0);
                vb.x = fmaf(vb.x, s1, b1); vb.y = fmaf(vb.y, s1, b1);
                vb.z = fmaf(vb.z, s1, b1); vb.w = fmaf(vb.w, s1, b1);
                float* op = out + ((size_t)(echunk * 32 + el) * ZPL + z) * NPX + 4 * pg;
                *(float4*)op = va;
                *(float4*)(op + (size_t)ZPL * NPX) = vb;
            }
        }
        return;
    }

    // ---------------- EXACT FALLBACK (bit-faithful per pixel) ----------------
    {
        float* sval = dyn;                 // [NPX * TPITCH]
        float nsum = 0.0f;
        const int pstart = w * 25;

        for (int i = 0; i < 25; i++) {
            const int p = pstart + i;
            const int y = p / 20;
            const int x = p - y * 20;

            float pyf = (float)y - p0 + 10.0f;
            float fy  = floorf(pyf);
            float dyy = pyf - fy;
            int   iy  = max(0, min((int)fy, SPL_H - 1));

            float pxf = (float)x - p1 + 10.0f;
            float fx  = floorf(pxf);
            float dxx = pxf - fx;
            int   ix  = max(0, min((int)fx, SPL_W - 1));

            float dxx2 = dxx * dxx, dxx3 = dxx2 * dxx;
            float dyy2 = dyy * dyy, dyy3 = dyy2 * dyy;

            const float4* cp = (const float4*)(coefs +
                (((size_t)(izoff + iy) * SPL_W + ix) << 6));

            float s[4];
            #pragma unroll
            for (int a = 0; a < 4; a++) {
                float4 c0 = cp[a * 4 + 0];
                float4 c1 = cp[a * 4 + 1];
                float4 c2 = cp[a * 4 + 2];
                float4 c3 = cp[a * 4 + 3];
                float t0 = fmaf(c0.w, dxx3, fmaf(c0.z, dxx2, fmaf(c0.y, dxx, c0.x)));
                float t1 = fmaf(c1.w, dxx3, fmaf(c1.z, dxx2, fmaf(c1.y, dxx, c1.x)));
                float t2 = fmaf(c2.w, dxx3, fmaf(c2.z, dxx2, fmaf(c2.y, dxx, c2.x)));
                float t3 = fmaf(c3.w, dxx3, fmaf(c3.z, dxx2, fmaf(c3.y, dxx, c3.x)));
                s[a] = fmaf(t3, dyy3, fmaf(t2, dyy2, fmaf(t1, dyy, t0)));
            }
            float v = fmaf(s[3], dz3, fmaf(s[2], dz2, fmaf(s[1], dz, s[0])));

            sval[p * TPITCH + lane] = v;
            nsum += v;
        }

        ssum[w][lane] = nsum;
        __syncthreads();

        const int el = 2 * w + (lane >> 4);
        float t = ssum[lane & 15][el];
        t += __shfl_xor_sync(0xffffffffu, t, 8);
        t += __shfl_xor_sync(0xffffffffu, t, 4);
        t += __shfl_xor_sync(0xffffffffu, t, 2);
        t += __shfl_xor_sync(0xffffffffu, t, 1);
        const float tot0 = __shfl_sync(0xffffffffu, t, 0);
        const float tot1 = __shfl_sync(0xffffffffu, t, 16);

        #pragma unroll
        for (int q = 0; q < 2; q++) {
            const int   elq = 2 * w + q;
            const int   eo  = echunk * 32 + elq;
            const float scq = inten[eo * ZPL + z] / (q ? tot1 : tot0);
            const float bgv = bg[eo * ZPL + z];
            float* op = out + ((size_t)eo * ZPL + z) * NPX;
            #pragma unroll
            for (int m = 0; m < 13; m++) {
                int pp = m * 32 + lane;
                if (pp < NPX) op[pp] = fmaf(sval[pp * TPITCH + elq], scq, bgv);
            }
        }
    }
}

extern "C" void kernel_launch(void* const* d_in, const int* in_sizes, int n_in,
                              void* d_out, int out_size)
{
    const float* pos   = (const float*)d_in[0];
    const float* inten = (const float*)d_in[1];
    const float* bg    = (const float*)d_in[2];
    const float* coefs = (const float*)d_in[3];

    const int smem = 64 * CPITCH * sizeof(float);   // 103.4 KB dynamic
    cudaFuncSetAttribute(psf_fused, cudaFuncAttributeMaxDynamicSharedMemorySize, smem);
    psf_fused<<<128, 512, smem>>>(pos, inten, bg, coefs, (float*)d_out);
}